// round 13
// baseline (speedup 1.0000x reference)
#include <cuda_runtime.h>
#include <cuda_fp16.h>
#include <cstdint>

#define BATCH 16
#define TSEQ  4096
#define DIM   256
#define CH    64
#define NC    (TSEQ/CH)          // 64 chunks

typedef unsigned int u32;
typedef unsigned short u16;

// ---------------- device scratch (allocation-free rule) ----------------
__device__ float g_E[BATCH * NC * DIM];             // chunk-final LOCAL h
__device__ int   g_epoch[BATCH * NC];               // per-CTA launch counter
__device__ int   g_ready;                           // += 128 per launch (B/C frags)
__device__ int   g_done[BATCH * NC];                // per-chunk epoch counters
// B / C pre-converted fp16 in mma fragment layout: [ks16][nt2_16][lane32][slot4]
__device__ __align__(16) u32 g_Bf[32768];
__device__ __align__(16) u32 g_Cf[32768];

// ---------------- helpers ----------------
__device__ __forceinline__ u16 f16_rn(float x) {
    return __half_as_ushort(__float2half_rn(x));
}
__device__ __forceinline__ u32 pack2(u16 a, u16 b) {
    return (u32)a | ((u32)b << 16);
}
__device__ __forceinline__ void mma_f16(float* c, const u32* a, u32 b0, u32 b1) {
    asm("mma.sync.aligned.m16n8k16.row.col.f32.f16.f16.f32 "
        "{%0,%1,%2,%3}, {%4,%5,%6,%7}, {%8,%9}, {%0,%1,%2,%3};"
        : "+f"(c[0]), "+f"(c[1]), "+f"(c[2]), "+f"(c[3])
        : "r"(a[0]), "r"(a[1]), "r"(a[2]), "r"(a[3]), "r"(b0), "r"(b1));
}

// ---------------- smem (disjoint regions) ----------------
// scanb: 64 x 260 floats = 66560 B at offset 0
// F    : fp16 A-fragments, 4 slabs x 8KB = 32768 B at offset 66560
#define OFF_F    66560
#define SMEM_SZ  (OFF_F + 32768)      // 99328 B; 2 CTA/SM fits 228KB carveout

// A-frag staging (fp16 rn), slab stride 8KB (2048 u32)
__device__ __forceinline__ void stage_A(u32* F, int row, int cp, float x, float y)
{
    int slab = row >> 4, rin = row & 15;
    int ks = cp >> 3, cpin = cp & 7;
    int lane = (rin & 7) * 4 + (cpin & 3);
    int reg  = ((cpin >> 2) << 1) | (rin >> 3);
    F[slab * 2048 + ((ks * 32 + lane) << 2) + reg] = pack2(f16_rn(x), f16_rn(y));
}

// Mainloop: warp tile m32 x n64 (2 M-slabs), single pass, B fp16 via LDG.
__device__ __forceinline__ void gemm_main(const u32* __restrict__ gBf,
                                          const u32* F,
                                          float acc[2][8][4], int wr, int wc, int lane)
{
    const u32* a0p = F + (wr * 2 + 0) * 2048 + lane * 4;
    const u32* a1p = F + (wr * 2 + 1) * 2048 + lane * 4;
    const u32* b_p = gBf + (wc * 4) * 128 + lane * 4;
    #pragma unroll
    for (int ks = 0; ks < 16; ++ks) {
        uint4 AH0 = *(const uint4*)(a0p + ks * 128);
        uint4 AH1 = *(const uint4*)(a1p + ks * 128);
        u32 ah[2][4] = {{AH0.x, AH0.y, AH0.z, AH0.w}, {AH1.x, AH1.y, AH1.z, AH1.w}};
        const u32* bp = b_p + ks * 2048;
        #pragma unroll
        for (int jp = 0; jp < 2; ++jp) {
            uint4 B0 = *(const uint4*)(bp + (2 * jp) * 128);
            uint4 B1 = *(const uint4*)(bp + (2 * jp + 1) * 128);
            #pragma unroll
            for (int s = 0; s < 2; ++s) {
                mma_f16(acc[s][4 * jp + 0], ah[s], B0.x, B0.y);
                mma_f16(acc[s][4 * jp + 1], ah[s], B0.z, B0.w);
                mma_f16(acc[s][4 * jp + 2], ah[s], B1.x, B1.y);
                mma_f16(acc[s][4 * jp + 3], ah[s], B1.z, B1.w);
            }
        }
    }
}

// ---------------------------------------------------------------------------
// kF: single fused kernel.
//   bid<128 CTAs also convert B/C to fp16 frags (replaces k0).
//   Epoch counters make the sync graph-replay safe with no reset pass.
//   grid (b=16, c=64): bid = c*16 + b, dependencies have smaller bids.
// ---------------------------------------------------------------------------
__global__ __launch_bounds__(256, 2) void kF(
    const float* __restrict__ U, const float* __restrict__ A,
    const float* __restrict__ h0v, float* __restrict__ Y,
    const float* __restrict__ Bm, const float* __restrict__ Cm)
{
    extern __shared__ __align__(16) char smem[];
    float* scanb = (float*)smem;
    u32* F = (u32*)(smem + OFF_F);
    __shared__ int sL;

    const int tid = threadIdx.x, wid = tid >> 5, lane = tid & 31;
    const int wr = wid & 1, wc = wid >> 1;
    const int b = blockIdx.x, c = blockIdx.y;
    const int bid = c * BATCH + b;
    const int t0 = c * CH;

    if (tid == 0) sL = atomicAdd(&g_epoch[bid], 1) + 1;   // this launch's epoch

    // ---- stage U tile as fp16 A-fragments
    {
        const float* ub = U + ((size_t)b * TSEQ + t0) * DIM;
        #pragma unroll
        for (int it = 0; it < 32; ++it) {
            int idx = tid + it * 256;          // 8192 = 64 rows x 128 colpairs
            int row = idx >> 7, cp = idx & 127;
            float2 v = *(const float2*)(ub + (size_t)row * DIM + cp * 2);
            stage_A(F, row, cp, v.x, v.y);
        }
    }

    // ---- converter CTAs: produce this launch's B/C fp16 fragments
    if (bid < 128) {
        int idx = bid * 256 + tid;             // 0..32767
        int slot  = idx & 3;
        int lane2 = (idx >> 2) & 31;
        int nt2   = (idx >> 7) & 15;
        int ks    = (idx >> 11) & 15;
        int ntlow = slot >> 1, breg = slot & 1;
        int n = (nt2 * 2 + ntlow) * 8 + (lane2 >> 2);
        int k = ks * 16 + (lane2 & 3) * 2 + breg * 8;
        g_Bf[idx] = pack2(f16_rn(Bm[(size_t)k * DIM + n]),
                          f16_rn(Bm[(size_t)(k + 1) * DIM + n]));
        g_Cf[idx] = pack2(f16_rn(Cm[(size_t)k * DIM + n]),
                          f16_rn(Cm[(size_t)(k + 1) * DIM + n]));
        __threadfence();
    }
    __syncthreads();
    const int L = sL;
    if (bid < 128 && tid == 0) atomicAdd(&g_ready, 1);

    // ---- wait until all 128 converter CTAs of this launch have published
    if (tid == 0) {
        while (atomicAdd(&g_ready, 0) < 128 * L) __nanosleep(32);
    }
    __syncthreads();

    float acc[2][8][4];
    #pragma unroll
    for (int s = 0; s < 2; ++s)
        #pragma unroll
        for (int i = 0; i < 8; ++i) {
            acc[s][i][0]=0.f; acc[s][i][1]=0.f; acc[s][i][2]=0.f; acc[s][i][3]=0.f;
        }
    gemm_main(g_Bf, F, acc, wr, wc, lane);

    // acc -> scanb (state-major for the scan); scanb disjoint from F
    #pragma unroll
    for (int s = 0; s < 2; ++s) {
        int r0 = (wr * 2 + s) * 16 + (lane >> 2);
        #pragma unroll
        for (int a = 0; a < 8; ++a) {
            int col = wc * 64 + (a >> 1) * 16 + (a & 1) * 8 + (lane & 3) * 2;
            scanb[r0 * 260 + col]           = acc[s][a][0];
            scanb[r0 * 260 + col + 1]       = acc[s][a][1];
            scanb[(r0 + 8) * 260 + col]     = acc[s][a][2];
            scanb[(r0 + 8) * 260 + col + 1] = acc[s][a][3];
        }
    }
    __syncthreads();

    // ---- pass 1: local E only
    const float a = A[tid];
    {
        float h = 0.f;
        #pragma unroll 8
        for (int t = 0; t < CH; ++t)
            h = fmaf(h, a, scanb[t * 260 + tid]);
        g_E[((size_t)b * NC + c) * DIM + tid] = h;
        __threadfence();
    }
    __syncthreads();
    if (tid == 0) atomicAdd(&g_done[b * NC + c], 1);

    // ---- parallel wait: thread j polls chunk j (j < c)
    if (tid < c) {
        while (atomicAdd(&g_done[b * NC + tid], 0) < L) __nanosleep(32);
    }
    __syncthreads();

    // ---- carry for this thread's state: scan of earlier chunks' E
    float carry = h0v[tid];
    {
        float p = a;
        #pragma unroll
        for (int i = 0; i < 6; ++i) p = p * p;          // a^64
        const float* Eb = g_E + (size_t)b * NC * DIM + tid;
        for (int j = 0; j < c; ++j)
            carry = fmaf(p, carry, Eb[(size_t)j * DIM]);
    }

    // ---- pass 2: exact reference scan seeded with carry; write F directly.
    // lane pair (tid, tid^1) packs two states into one u32 frag write.
    {
        const int cp = tid >> 1;
        const int ks = cp >> 3, cpin = cp & 7;
        const int lbase = (cpin & 3);
        const int rsel  = ((cpin >> 2) << 1);
        float h = carry;
        #pragma unroll 8
        for (int t = 0; t < CH; ++t) {
            h = fmaf(h, a, scanb[t * 260 + tid]);
            u32 mine = f16_rn(h);
            u32 part = __shfl_xor_sync(0xffffffffu, mine, 1);
            if (!(tid & 1)) {
                int slab = t >> 4, rin = t & 15;
                int lane2 = (rin & 7) * 4 + lbase;
                int reg   = rsel | (rin >> 3);
                F[slab * 2048 + ((ks * 32 + lane2) << 2) + reg] =
                    pack2((u16)mine, (u16)part);
            }
        }
    }
    __syncthreads();

    // ---- GEMM with C
    #pragma unroll
    for (int s = 0; s < 2; ++s)
        #pragma unroll
        for (int i = 0; i < 8; ++i) {
            acc[s][i][0]=0.f; acc[s][i][1]=0.f; acc[s][i][2]=0.f; acc[s][i][3]=0.f;
        }
    gemm_main(g_Cf, F, acc, wr, wc, lane);

    // ---- epilogue: store acc directly to Y (float2, full-sector STG)
    {
        float* yb = Y + ((size_t)b * TSEQ + t0) * DIM;
        #pragma unroll
        for (int s = 0; s < 2; ++s) {
            int r0 = (wr * 2 + s) * 16 + (lane >> 2);
            #pragma unroll
            for (int aa = 0; aa < 8; ++aa) {
                int col = wc * 64 + (aa >> 1) * 16 + (aa & 1) * 8 + (lane & 3) * 2;
                *(float2*)(yb + (size_t)r0 * DIM + col) =
                    make_float2(acc[s][aa][0], acc[s][aa][1]);
                *(float2*)(yb + (size_t)(r0 + 8) * DIM + col) =
                    make_float2(acc[s][aa][2], acc[s][aa][3]);
            }
        }
    }
}

// ---------------------------------------------------------------------------

extern "C" void kernel_launch(void* const* d_in, const int* in_sizes, int n_in,
                              void* d_out, int out_size)
{
    const float* U  = (const float*)d_in[0];
    const float* A  = (const float*)d_in[1];
    const float* Bm = (const float*)d_in[2];
    const float* Cm = (const float*)d_in[3];
    const float* h0 = (const float*)d_in[4];
    float* Y = (float*)d_out;
    (void)in_sizes; (void)n_in; (void)out_size;

    cudaFuncSetAttribute(kF, cudaFuncAttributeMaxDynamicSharedMemorySize, SMEM_SZ);

    kF<<<dim3(BATCH, NC), 256, SMEM_SZ>>>(U, A, h0, Y, Bm, Cm);
}

// round 14
// speedup vs baseline: 1.1303x; 1.1303x over previous
#include <cuda_runtime.h>
#include <cuda_fp16.h>
#include <cstdint>

#define BATCH 16
#define TSEQ  4096
#define DIM   256
#define CH    64
#define NC    (TSEQ/CH)          // 64 chunks

typedef unsigned int u32;
typedef unsigned short u16;
typedef unsigned long long u64;

// ---------------- device scratch (allocation-free rule) ----------------
__device__ float g_E[BATCH * NC * DIM];             // chunk-final LOCAL h
__device__ u64   g_mask[BATCH];                     // per-batch chunk-done bitmask
// B / C pre-converted fp16 in mma fragment layout: [ks16][nt2_16][lane32][slot4]
__device__ __align__(16) u32 g_Bf[32768];
__device__ __align__(16) u32 g_Cf[32768];

// ---------------- helpers ----------------
__device__ __forceinline__ u16 f16_rn(float x) {
    return __half_as_ushort(__float2half_rn(x));
}
__device__ __forceinline__ u32 pack2(u16 a, u16 b) {
    return (u32)a | ((u32)b << 16);
}
__device__ __forceinline__ void mma_f16(float* c, const u32* a, u32 b0, u32 b1) {
    asm("mma.sync.aligned.m16n8k16.row.col.f32.f16.f16.f32 "
        "{%0,%1,%2,%3}, {%4,%5,%6,%7}, {%8,%9}, {%0,%1,%2,%3};"
        : "+f"(c[0]), "+f"(c[1]), "+f"(c[2]), "+f"(c[3])
        : "r"(a[0]), "r"(a[1]), "r"(a[2]), "r"(a[3]), "r"(b0), "r"(b1));
}

// ---------------------------------------------------------------------------
// k0: convert B and C to fp16 fragment layout; zero the chunk masks.
// ---------------------------------------------------------------------------
__global__ void k0_convert(const float* __restrict__ Bm, const float* __restrict__ Cm)
{
    if (blockIdx.x == 0 && threadIdx.x < BATCH) g_mask[threadIdx.x] = 0ull;

    int idx = blockIdx.x * 256 + threadIdx.x;        // 0..32767
    int slot  = idx & 3;
    int lane  = (idx >> 2) & 31;
    int nt2   = (idx >> 7) & 15;
    int ks    = (idx >> 11) & 15;                    // k-step 0..15
    int ntlow = slot >> 1, breg = slot & 1;
    int n = (nt2 * 2 + ntlow) * 8 + (lane >> 2);
    int k = ks * 16 + (lane & 3) * 2 + breg * 8;

    g_Bf[idx] = pack2(f16_rn(Bm[(size_t)k * DIM + n]),
                      f16_rn(Bm[(size_t)(k + 1) * DIM + n]));
    g_Cf[idx] = pack2(f16_rn(Cm[(size_t)k * DIM + n]),
                      f16_rn(Cm[(size_t)(k + 1) * DIM + n]));
}

// ---------------- smem (disjoint regions) ----------------
// scanb: 64 x 260 floats = 66560 B at offset 0
// F    : fp16 A-fragments, 4 slabs x 8KB = 32768 B at offset 66560
#define OFF_F    66560
#define SMEM_SZ  (OFF_F + 32768)      // 99328 B; 2 CTA/SM fits 228KB carveout

// A-frag staging (fp16 rn), slab stride 8KB (2048 u32)
__device__ __forceinline__ void stage_A(u32* F, int row, int cp, float x, float y)
{
    int slab = row >> 4, rin = row & 15;
    int ks = cp >> 3, cpin = cp & 7;
    int lane = (rin & 7) * 4 + (cpin & 3);
    int reg  = ((cpin >> 2) << 1) | (rin >> 3);
    F[slab * 2048 + ((ks * 32 + lane) << 2) + reg] = pack2(f16_rn(x), f16_rn(y));
}

// Mainloop: warp tile m32 x n64 (2 M-slabs), single pass, B fp16 via LDG.
__device__ __forceinline__ void gemm_main(const u32* __restrict__ gBf,
                                          const u32* F,
                                          float acc[2][8][4], int wr, int wc, int lane)
{
    const u32* a0p = F + (wr * 2 + 0) * 2048 + lane * 4;
    const u32* a1p = F + (wr * 2 + 1) * 2048 + lane * 4;
    const u32* b_p = gBf + (wc * 4) * 128 + lane * 4;
    #pragma unroll
    for (int ks = 0; ks < 16; ++ks) {
        uint4 AH0 = *(const uint4*)(a0p + ks * 128);
        uint4 AH1 = *(const uint4*)(a1p + ks * 128);
        u32 ah[2][4] = {{AH0.x, AH0.y, AH0.z, AH0.w}, {AH1.x, AH1.y, AH1.z, AH1.w}};
        const u32* bp = b_p + ks * 2048;
        #pragma unroll
        for (int jp = 0; jp < 2; ++jp) {
            uint4 B0 = *(const uint4*)(bp + (2 * jp) * 128);
            uint4 B1 = *(const uint4*)(bp + (2 * jp + 1) * 128);
            #pragma unroll
            for (int s = 0; s < 2; ++s) {
                mma_f16(acc[s][4 * jp + 0], ah[s], B0.x, B0.y);
                mma_f16(acc[s][4 * jp + 1], ah[s], B0.z, B0.w);
                mma_f16(acc[s][4 * jp + 2], ah[s], B1.x, B1.y);
                mma_f16(acc[s][4 * jp + 3], ah[s], B1.z, B1.w);
            }
        }
    }
}

// ---------------------------------------------------------------------------
// kF: fused  Bu = U@B -> E pass -> publish -> wait -> carry -> exact scan
//     (writes F directly) -> Y = h@C (direct STG).  256 thr, 2 CTA/SM.
//     grid (b=16, c=64): bid = c*16 + b, dependencies have smaller bids.
// ---------------------------------------------------------------------------
__global__ __launch_bounds__(256, 2) void kF(
    const float* __restrict__ U, const float* __restrict__ A,
    const float* __restrict__ h0v, float* __restrict__ Y)
{
    extern __shared__ __align__(16) char smem[];
    float* scanb = (float*)smem;
    u32* F = (u32*)(smem + OFF_F);

    const int tid = threadIdx.x, wid = tid >> 5, lane = tid & 31;
    const int wr = wid & 1, wc = wid >> 1;
    const int b = blockIdx.x, c = blockIdx.y;
    const int t0 = c * CH;

    // ---- stage U tile as fp16 A-fragments
    {
        const float* ub = U + ((size_t)b * TSEQ + t0) * DIM;
        #pragma unroll
        for (int it = 0; it < 32; ++it) {
            int idx = tid + it * 256;          // 8192 = 64 rows x 128 colpairs
            int row = idx >> 7, cp = idx & 127;
            float2 v = *(const float2*)(ub + (size_t)row * DIM + cp * 2);
            stage_A(F, row, cp, v.x, v.y);
        }
    }
    __syncthreads();

    float acc[2][8][4];
    #pragma unroll
    for (int s = 0; s < 2; ++s)
        #pragma unroll
        for (int i = 0; i < 8; ++i) {
            acc[s][i][0]=0.f; acc[s][i][1]=0.f; acc[s][i][2]=0.f; acc[s][i][3]=0.f;
        }
    gemm_main(g_Bf, F, acc, wr, wc, lane);

    // acc -> scanb (state-major for the scan); scanb disjoint from F
    #pragma unroll
    for (int s = 0; s < 2; ++s) {
        int r0 = (wr * 2 + s) * 16 + (lane >> 2);
        #pragma unroll
        for (int a = 0; a < 8; ++a) {
            int col = wc * 64 + (a >> 1) * 16 + (a & 1) * 8 + (lane & 3) * 2;
            scanb[r0 * 260 + col]           = acc[s][a][0];
            scanb[r0 * 260 + col + 1]       = acc[s][a][1];
            scanb[(r0 + 8) * 260 + col]     = acc[s][a][2];
            scanb[(r0 + 8) * 260 + col + 1] = acc[s][a][3];
        }
    }
    __syncthreads();

    // ---- pass 1: local E only (software-pipelined: load 8 ahead)
    const float a = A[tid];
    {
        float h = 0.f;
        float buf[8], nxt[8];
        #pragma unroll
        for (int i = 0; i < 8; ++i) buf[i] = scanb[i * 260 + tid];
        #pragma unroll
        for (int g = 0; g < 8; ++g) {
            if (g < 7) {
                #pragma unroll
                for (int i = 0; i < 8; ++i)
                    nxt[i] = scanb[((g + 1) * 8 + i) * 260 + tid];
            }
            #pragma unroll
            for (int i = 0; i < 8; ++i) h = fmaf(h, a, buf[i]);
            #pragma unroll
            for (int i = 0; i < 8; ++i) buf[i] = nxt[i];
        }
        g_E[((size_t)b * NC + c) * DIM + tid] = h;
    }
    __syncthreads();
    if (tid == 0) {
        __threadfence();
        atomicOr(&g_mask[b], 1ull << c);
    }

    // ---- wait for all earlier chunks of this batch
    const u64 need = (1ull << c) - 1ull;
    if (tid == 0 && need) {
        while ((atomicOr(&g_mask[b], 0ull) & need) != need) __nanosleep(64);
        __threadfence();
    }
    __syncthreads();

    // ---- carry: scan of earlier chunks' E, batched loads (MLP=4)
    float carry = h0v[tid];
    {
        float p = a;
        #pragma unroll
        for (int i = 0; i < 6; ++i) p = p * p;          // a^64
        const float* Eb = g_E + (size_t)b * NC * DIM + tid;
        int j = 0;
        for (; j + 4 <= c; j += 4) {
            float e0 = Eb[(size_t)(j + 0) * DIM];
            float e1 = Eb[(size_t)(j + 1) * DIM];
            float e2 = Eb[(size_t)(j + 2) * DIM];
            float e3 = Eb[(size_t)(j + 3) * DIM];
            carry = fmaf(p, carry, e0);
            carry = fmaf(p, carry, e1);
            carry = fmaf(p, carry, e2);
            carry = fmaf(p, carry, e3);
        }
        for (; j < c; ++j)
            carry = fmaf(p, carry, Eb[(size_t)j * DIM]);
    }

    // ---- pass 2: exact reference scan seeded with carry; write F directly.
    // Software-pipelined loads; lane pair (tid, tid^1) packs two states/u32.
    {
        const int cp = tid >> 1;
        const int ks = cp >> 3, cpin = cp & 7;
        const int lbase = (cpin & 3);
        const int rsel  = ((cpin >> 2) << 1);
        float h = carry;
        float buf[8], nxt[8];
        #pragma unroll
        for (int i = 0; i < 8; ++i) buf[i] = scanb[i * 260 + tid];
        #pragma unroll
        for (int g = 0; g < 8; ++g) {
            if (g < 7) {
                #pragma unroll
                for (int i = 0; i < 8; ++i)
                    nxt[i] = scanb[((g + 1) * 8 + i) * 260 + tid];
            }
            #pragma unroll
            for (int i = 0; i < 8; ++i) {
                int t = g * 8 + i;
                h = fmaf(h, a, buf[i]);
                u32 mine = f16_rn(h);
                u32 part = __shfl_xor_sync(0xffffffffu, mine, 1);
                if (!(tid & 1)) {
                    int slab = t >> 4, rin = t & 15;
                    int lane2 = (rin & 7) * 4 + lbase;
                    int reg   = rsel | (rin >> 3);
                    F[slab * 2048 + ((ks * 32 + lane2) << 2) + reg] =
                        pack2((u16)mine, (u16)part);
                }
            }
            #pragma unroll
            for (int i = 0; i < 8; ++i) buf[i] = nxt[i];
        }
    }
    __syncthreads();

    // ---- GEMM with C
    #pragma unroll
    for (int s = 0; s < 2; ++s)
        #pragma unroll
        for (int i = 0; i < 8; ++i) {
            acc[s][i][0]=0.f; acc[s][i][1]=0.f; acc[s][i][2]=0.f; acc[s][i][3]=0.f;
        }
    gemm_main(g_Cf, F, acc, wr, wc, lane);

    // ---- epilogue: store acc directly to Y (float2, full-sector STG)
    {
        float* yb = Y + ((size_t)b * TSEQ + t0) * DIM;
        #pragma unroll
        for (int s = 0; s < 2; ++s) {
            int r0 = (wr * 2 + s) * 16 + (lane >> 2);
            #pragma unroll
            for (int aa = 0; aa < 8; ++aa) {
                int col = wc * 64 + (aa >> 1) * 16 + (aa & 1) * 8 + (lane & 3) * 2;
                *(float2*)(yb + (size_t)r0 * DIM + col) =
                    make_float2(acc[s][aa][0], acc[s][aa][1]);
                *(float2*)(yb + (size_t)(r0 + 8) * DIM + col) =
                    make_float2(acc[s][aa][2], acc[s][aa][3]);
            }
        }
    }
}

// ---------------------------------------------------------------------------

extern "C" void kernel_launch(void* const* d_in, const int* in_sizes, int n_in,
                              void* d_out, int out_size)
{
    const float* U  = (const float*)d_in[0];
    const float* A  = (const float*)d_in[1];
    const float* Bm = (const float*)d_in[2];
    const float* Cm = (const float*)d_in[3];
    const float* h0 = (const float*)d_in[4];
    float* Y = (float*)d_out;
    (void)in_sizes; (void)n_in; (void)out_size;

    cudaFuncSetAttribute(kF, cudaFuncAttributeMaxDynamicSharedMemorySize, SMEM_SZ);

    k0_convert<<<128, 256>>>(Bm, Cm);
    kF<<<dim3(BATCH, NC), 256, SMEM_SZ>>>(U, A, h0, Y);
}